// round 15
// baseline (speedup 1.0000x reference)
#include <cuda_runtime.h>
#include <math.h>

typedef unsigned long long ull;
#define BN_EPS 1e-5f

// ---------------- scratch ----------------
__device__ float g_pool[8 * 64 * 32 * 32];
__device__ float g_w2t[576 * 128];
__device__ float g_nodes0[8192 * 128];
__device__ float g_h1[8192 * 256];
__device__ float g_x1[8192 * 256];
__device__ float g_h2[8192 * 128];
__device__ float g_x2[8192 * 128];
__device__ float g_s1p[1024 * 4];
__device__ float g_d1p[1024 * 4];
__device__ float g_s2p[1024 * 2];
__device__ float g_d2p[1024 * 2];
__device__ float g_psum[1024 * 8];
__device__ float g_apart[32 * 1024 * 128];   // 16 MB: NP x 1024 x D (NP*D = 4096 both layers)

// ---------------- f32x2 helpers ----------------
__device__ __forceinline__ unsigned sptr(const void* p) {
    return (unsigned)__cvta_generic_to_shared(p);
}
__device__ __forceinline__ void lds2(ull& a, ull& b, unsigned addr) {
    asm volatile("ld.shared.v2.b64 {%0,%1},[%2];" : "=l"(a), "=l"(b) : "r"(addr));
}
__device__ __forceinline__ ull dupf(float v) {
    unsigned u = __float_as_uint(v);
    ull r;
    asm("mov.b64 %0,{%1,%1};" : "=l"(r) : "r"(u));
    return r;
}
__device__ __forceinline__ void ffma2(ull& d, ull a, ull b) {
    asm("fma.rn.f32x2 %0,%1,%2,%0;" : "+l"(d) : "l"(a), "l"(b));
}
union F2U { ull u; float2 f; };
__device__ __forceinline__ float2 upk(ull u) { F2U x; x.u = u; return x.f; }

// ---------------- stage1: conv1+bn+relu+pool | w2 transpose ----------------
__global__ __launch_bounds__(256) void stage1_kernel(
    const float* __restrict__ img, const float* __restrict__ w,
    const float* __restrict__ cb, const float* __restrict__ g,
    const float* __restrict__ bb, const float* __restrict__ m,
    const float* __restrict__ v, const float* __restrict__ w2)
{
    __shared__ float ws[1728];
    __shared__ float sc_s[64], sh_s[64];
    int t = threadIdx.x;

    if (blockIdx.x >= 2048) {
        int i = (blockIdx.x - 2048) * 256 + t;      // 73728 total
        int rem = i >> 7, oc = i & 127;
        g_w2t[i] = w2[oc * 576 + rem];
        return;
    }

    for (int i = t; i < 1728; i += 256) ws[i] = w[i];
    if (t < 64) {
        float sc = g[t] * rsqrtf(v[t] + BN_EPS);
        sc_s[t] = sc;
        sh_s[t] = bb[t] - m[t] * sc + cb[t] * sc;
    }
    __syncthreads();

    int idx = blockIdx.x * 256 + t;
    int pw = idx & 31;
    int ph = (idx >> 5) & 31;
    int c  = (idx >> 10) & 63;
    int b  = idx >> 16;

    float win[3][4][4];
    int h0 = 2 * ph - 1, w0 = 2 * pw - 1;
#pragma unroll
    for (int ic = 0; ic < 3; ic++) {
        const float* ip = img + (b * 3 + ic) * 4096;
#pragma unroll
        for (int r = 0; r < 4; r++) {
            int ih = h0 + r;
            bool rok = (unsigned)ih < 64u;
#pragma unroll
            for (int cc = 0; cc < 4; cc++) {
                int iw = w0 + cc;
                win[ic][r][cc] = (rok && (unsigned)iw < 64u) ? ip[ih * 64 + iw] : 0.0f;
            }
        }
    }
    const float* wc = ws + c * 27;
    float sc = sc_s[c], sh = sh_s[c];
    float mx = 0.0f;
#pragma unroll
    for (int dh = 0; dh < 2; dh++)
#pragma unroll
    for (int dw = 0; dw < 2; dw++) {
        float s = 0.f;
#pragma unroll
        for (int ic = 0; ic < 3; ic++)
#pragma unroll
        for (int kh = 0; kh < 3; kh++)
#pragma unroll
        for (int kw = 0; kw < 3; kw++)
            s += win[ic][dh + kh][dw + kw] * wc[ic * 9 + kh * 3 + kw];
        float y = s * sc + sh;
        y = y > 0.f ? y : 0.f;
        mx = fmaxf(mx, y);
    }
    g_pool[idx] = mx;
}

// ---------------- conv2: grid (16 row-pairs, 2 oc-halves, 8 imgs) ----------------
__global__ __launch_bounds__(256) void conv2_kernel(
    const float* __restrict__ cb, const float* __restrict__ g,
    const float* __restrict__ bb, const float* __restrict__ m,
    const float* __restrict__ v)
{
    __shared__ float in_s[1088];   // 8ic x 4rows x 34cols
    __shared__ float w_s[4608];    // 72 x 64
    int t  = threadIdx.x;
    int h0 = blockIdx.x * 2;
    int oh = blockIdx.y;
    int b  = blockIdx.z;
    int px = t & 31;
    int cq = t >> 5;
    unsigned wsa = sptr(w_s);

    ull acc[2][4];
#pragma unroll
    for (int r = 0; r < 2; r++)
#pragma unroll
    for (int j = 0; j < 4; j++) acc[r][j] = 0ull;

    const float4* w2t4 = (const float4*)g_w2t;
    for (int ic0 = 0; ic0 < 64; ic0 += 8) {
        __syncthreads();
        for (int i = t; i < 1152; i += 256) {
            int rem = i >> 4, q = i & 15;
            ((float4*)w_s)[i] = w2t4[(ic0 * 9 + rem) * 32 + oh * 16 + q];
        }
        for (int i = t; i < 1088; i += 256) {
            int ic  = i / 136;
            int rem = i - ic * 136;
            int r   = rem / 34;
            int col = rem - r * 34;
            int ri = h0 - 1 + r;
            int ci = col - 1;
            float val = 0.f;
            if ((unsigned)ri < 32u && (unsigned)ci < 32u)
                val = g_pool[((b * 64 + ic0 + ic) * 32 + ri) * 32 + ci];
            in_s[i] = val;
        }
        __syncthreads();
#pragma unroll 2
        for (int ic8 = 0; ic8 < 8; ic8++) {
#pragma unroll
            for (int kr = 0; kr < 3; kr++) {
                const float* prow = in_s + (ic8 * 4 + kr) * 34 + px;
#pragma unroll
                for (int kc = 0; kc < 3; kc++) {
                    unsigned wa = wsa + (((ic8 * 9 + kr * 3 + kc) << 6) + (cq << 3)) * 4u;
                    ull w0, w1, w2x, w3;
                    lds2(w0, w1, wa);
                    lds2(w2x, w3, wa + 16);
                    ull v0 = dupf(prow[kc]);
                    ull v1 = dupf(prow[kc + 34]);
                    ffma2(acc[0][0], v0, w0);  ffma2(acc[0][1], v0, w1);
                    ffma2(acc[0][2], v0, w2x); ffma2(acc[0][3], v0, w3);
                    ffma2(acc[1][0], v1, w0);  ffma2(acc[1][1], v1, w1);
                    ffma2(acc[1][2], v1, w2x); ffma2(acc[1][3], v1, w3);
                }
            }
        }
    }

    int cbase = oh * 64 + cq * 8;
    float scs[8], shs[8];
#pragma unroll
    for (int j = 0; j < 8; j++) {
        int c = cbase + j;
        float sc = g[c] * rsqrtf(v[c] + BN_EPS);
        scs[j] = sc;
        shs[j] = bb[c] - m[c] * sc + cb[c] * sc;
    }
#pragma unroll
    for (int r = 0; r < 2; r++) {
        int node = b * 1024 + (h0 + r) * 32 + px;
        float* op = g_nodes0 + node * 128 + cbase;
        float outv[8];
#pragma unroll
        for (int jp = 0; jp < 4; jp++) {
            float2 p = upk(acc[r][jp]);
            outv[2 * jp]     = p.x;
            outv[2 * jp + 1] = p.y;
        }
#pragma unroll
        for (int j = 0; j < 8; j++) {
            float y = outv[j] * scs[j] + shs[j];
            outv[j] = y > 0.f ? y : 0.f;
        }
        *(float4*)op       = *(float4*)&outv[0];
        *(float4*)(op + 4) = *(float4*)&outv[4];
    }
}

// ---------------- SGEMM: 128x64 tile, 8x4/thread, double-buffered, fused epilogue ----------------
__global__ __launch_bounds__(256) void sgemm_fused(
    const float* __restrict__ A, const float* __restrict__ B,
    const float* __restrict__ bias, const float* __restrict__ asrc,
    const float* __restrict__ adst, float* __restrict__ H,
    float* __restrict__ X, float* __restrict__ s_part,
    float* __restrict__ d_part, int N, int K)
{
    __shared__ float As[2][16][128];
    __shared__ float Bs[2][16][64];
    int t = threadIdx.x;
    int bm = blockIdx.y * 128, bn = blockIdx.x * 64;
    int tx = t & 15, ty = t >> 4;
    int ar = t >> 1, a8 = (t & 1) * 8;
    int bk = t >> 4, bc = (t & 15) * 4;
    const float* Aload = A + (size_t)(bm + ar) * K + a8;
    const float* Bload = B + (size_t)bk * N + bn + bc;
    unsigned bsB = sptr(Bs);

    float4 pa0 = *(const float4*)(Aload);
    float4 pa1 = *(const float4*)(Aload + 4);
    float4 pb  = *(const float4*)(Bload);

    ull acc[8][2];
#pragma unroll
    for (int i = 0; i < 8; i++) { acc[i][0] = 0ull; acc[i][1] = 0ull; }

    int NC = K >> 4;
    for (int ch = 0; ch < NC; ch++) {
        int p = ch & 1;
        As[p][a8 + 0][ar] = pa0.x; As[p][a8 + 1][ar] = pa0.y;
        As[p][a8 + 2][ar] = pa0.z; As[p][a8 + 3][ar] = pa0.w;
        As[p][a8 + 4][ar] = pa1.x; As[p][a8 + 5][ar] = pa1.y;
        As[p][a8 + 6][ar] = pa1.z; As[p][a8 + 7][ar] = pa1.w;
        *(float4*)&Bs[p][bk][bc] = pb;
        __syncthreads();
        if (ch + 1 < NC) {
            pa0 = *(const float4*)(Aload + (ch + 1) * 16);
            pa1 = *(const float4*)(Aload + (ch + 1) * 16 + 4);
            pb  = *(const float4*)(Bload + (size_t)(ch + 1) * 16 * N);
        }
        unsigned bbase = bsB + (unsigned)p * 4096u + (unsigned)tx * 16u;
#pragma unroll
        for (int k = 0; k < 16; k++) {
            float4 a0 = *(const float4*)&As[p][k][ty * 8];
            float4 a1 = *(const float4*)&As[p][k][ty * 8 + 4];
            ull b01, b23;
            lds2(b01, b23, bbase + (unsigned)k * 256u);
            ull d;
            d = dupf(a0.x); ffma2(acc[0][0], d, b01); ffma2(acc[0][1], d, b23);
            d = dupf(a0.y); ffma2(acc[1][0], d, b01); ffma2(acc[1][1], d, b23);
            d = dupf(a0.z); ffma2(acc[2][0], d, b01); ffma2(acc[2][1], d, b23);
            d = dupf(a0.w); ffma2(acc[3][0], d, b01); ffma2(acc[3][1], d, b23);
            d = dupf(a1.x); ffma2(acc[4][0], d, b01); ffma2(acc[4][1], d, b23);
            d = dupf(a1.y); ffma2(acc[5][0], d, b01); ffma2(acc[5][1], d, b23);
            d = dupf(a1.z); ffma2(acc[6][0], d, b01); ffma2(acc[6][1], d, b23);
            d = dupf(a1.w); ffma2(acc[7][0], d, b01); ffma2(acc[7][1], d, b23);
        }
    }

    float c[8][4];
#pragma unroll
    for (int rr = 0; rr < 8; rr++) {
        float2 lo = upk(acc[rr][0]);
        float2 hi = upk(acc[rr][1]);
        c[rr][0] = lo.x; c[rr][1] = lo.y; c[rr][2] = hi.x; c[rr][3] = hi.y;
    }
    int col = bn + tx * 4;

    if (bm >= 1024) {
        float4 bv = *(const float4*)&bias[col];
#pragma unroll
        for (int rr = 0; rr < 8; rr++) {
            float y0 = c[rr][0] + bv.x; y0 = y0 > 0.f ? y0 : 0.f;
            float y1 = c[rr][1] + bv.y; y1 = y1 > 0.f ? y1 : 0.f;
            float y2 = c[rr][2] + bv.z; y2 = y2 > 0.f ? y2 : 0.f;
            float y3 = c[rr][3] + bv.w; y3 = y3 > 0.f ? y3 : 0.f;
            *(float4*)&X[(size_t)(bm + ty * 8 + rr) * N + col] =
                make_float4(y0, y1, y2, y3);
        }
    } else {
        float4 av = *(const float4*)&asrc[col];
        float4 dv = *(const float4*)&adst[col];
        int NB = gridDim.x;
#pragma unroll
        for (int rr = 0; rr < 8; rr++) {
            *(float4*)&H[(size_t)(bm + ty * 8 + rr) * N + col] =
                make_float4(c[rr][0], c[rr][1], c[rr][2], c[rr][3]);
            float sp = c[rr][0] * av.x + c[rr][1] * av.y + c[rr][2] * av.z + c[rr][3] * av.w;
            float dp = c[rr][0] * dv.x + c[rr][1] * dv.y + c[rr][2] * dv.z + c[rr][3] * dv.w;
#pragma unroll
            for (int off = 8; off > 0; off >>= 1) {
                sp += __shfl_xor_sync(0xffffffffu, sp, off);
                dp += __shfl_xor_sync(0xffffffffu, dp, off);
            }
            if ((t & 15) == 0) {
                int row = bm + ty * 8 + rr;
                s_part[row * NB + blockIdx.x] = sp;
                d_part[row * NB + blockIdx.x] = dp;
            }
        }
    }
}

// ---------------- attention partial v4 (measured-best) ----------------
// grid (64 j-blocks of NJ=16, 8 i-splits of 128 rows) = 512 blocks.
// Direct g_apart partial writes per (by, ig) group; fused sd_combine.
template <int D, int NB>
__global__ __launch_bounds__(256) void attn_partial(
    const float* __restrict__ h, const float* __restrict__ s_part,
    const float* __restrict__ d_part)
{
    const int NJ = 16, IROWS = 128, PAD = 20;
    const int FG  = D / 4;             // 64 (D=256) / 32 (D=128)
    const int IGn = 256 / (FG * 2);    // 2 / 4
    const int RPI = IROWS / IGn;       // 64 / 32
    __shared__ float s_loc[IROWS];
    __shared__ float w_s[IROWS * PAD];     // 10 KB
    __shared__ float dv_s[NJ], mx_s[NJ];
    __shared__ float wred[8];
    __shared__ float smax_sh;
    int t = threadIdx.x;
    int j0 = blockIdx.x * NJ;
    int by = blockIdx.y;
    int i0 = by * IROWS;

    // fused sd_combine: all 1024 s sums (keep our 128), global max, our 16 d's
    float lmax = -1e30f;
#pragma unroll
    for (int k = 0; k < 4; k++) {
        int i = t + k * 256;
        float s = 0.f;
#pragma unroll
        for (int nb = 0; nb < NB; nb++) s += s_part[i * NB + nb];
        if ((unsigned)(i - i0) < (unsigned)IROWS) s_loc[i - i0] = s;
        lmax = fmaxf(lmax, s);
    }
    if (t < NJ) {
        float dd = 0.f;
#pragma unroll
        for (int nb = 0; nb < NB; nb++) dd += d_part[(j0 + t) * NB + nb];
        dv_s[t] = dd;
    }
#pragma unroll
    for (int o = 16; o > 0; o >>= 1)
        lmax = fmaxf(lmax, __shfl_xor_sync(0xffffffffu, lmax, o));
    if ((t & 31) == 0) wred[t >> 5] = lmax;
    __syncthreads();
    if (t == 0) {
        float mv = wred[0];
#pragma unroll
        for (int k = 1; k < 8; k++) mv = fmaxf(mv, wred[k]);
        smax_sh = mv;
    }
    __syncthreads();
    if (t < NJ) {
        float e = smax_sh + dv_s[t];
        mx_s[t] = e > 0.f ? e : 0.2f * e;
    }
    __syncthreads();

    // phase 1: w for this block's 128 rows x 16 j
    {
        int il = t & 127, jh = t >> 7;
        float si = s_loc[il];
#pragma unroll
        for (int jj = 0; jj < 8; jj++) {
            int j = jh * 8 + jj;
            float e = si + dv_s[j];
            e = e > 0.f ? e : 0.2f * e;
            w_s[il * PAD + j] = __expf(e - mx_s[j]);
        }
    }
    __syncthreads();

    // partial denominators
    {
        int lane = t & 31, wj = t >> 5;
#pragma unroll
        for (int c = wj; c < NJ; c += 8) {
            float sval = 0.f;
            for (int r = lane; r < IROWS; r += 32) sval += w_s[r * PAD + c];
#pragma unroll
            for (int o = 16; o > 0; o >>= 1)
                sval += __shfl_xor_sync(0xffffffffu, sval, o);
            if (lane == 0) g_psum[(j0 + c) * 8 + by] = sval;
        }
    }

    // phase 2: thread = (4 features fg, 8 dests jq-half, i-subrange ig)
    int fg = t & (FG - 1);
    int jq = (t / FG) & 1;
    int ig = t / (FG * 2);
    ull acc2[8][2];
#pragma unroll
    for (int j = 0; j < 8; j++) { acc2[j][0] = 0ull; acc2[j][1] = 0ull; }
    const float* hp = h + (size_t)(i0 + ig * RPI) * D + fg * 4;
    const float* wp = w_s + (ig * RPI) * PAD + jq * 8;
#pragma unroll 4
    for (int ii = 0; ii < RPI; ii++) {
        ulonglong2 hv = *(const ulonglong2*)(hp + (size_t)ii * D);
        float4 w0 = *(const float4*)(wp + ii * PAD);
        float4 w1 = *(const float4*)(wp + ii * PAD + 4);
        ull d;
        d = dupf(w0.x); ffma2(acc2[0][0], d, hv.x); ffma2(acc2[0][1], d, hv.y);
        d = dupf(w0.y); ffma2(acc2[1][0], d, hv.x); ffma2(acc2[1][1], d, hv.y);
        d = dupf(w0.z); ffma2(acc2[2][0], d, hv.x); ffma2(acc2[2][1], d, hv.y);
        d = dupf(w0.w); ffma2(acc2[3][0], d, hv.x); ffma2(acc2[3][1], d, hv.y);
        d = dupf(w1.x); ffma2(acc2[4][0], d, hv.x); ffma2(acc2[4][1], d, hv.y);
        d = dupf(w1.y); ffma2(acc2[5][0], d, hv.x); ffma2(acc2[5][1], d, hv.y);
        d = dupf(w1.z); ffma2(acc2[6][0], d, hv.x); ffma2(acc2[6][1], d, hv.y);
        d = dupf(w1.w); ffma2(acc2[7][0], d, hv.x); ffma2(acc2[7][1], d, hv.y);
    }

    // direct write of this (by, ig) group's unnormalized partial
    size_t p = (size_t)by * IGn + ig;
#pragma unroll
    for (int jj = 0; jj < 8; jj++) {
        int j = jq * 8 + jj;
        float2 lo = upk(acc2[jj][0]);
        float2 hi = upk(acc2[jj][1]);
        *(float4*)&g_apart[(p * 1024 + j0 + j) * D + fg * 4] =
            make_float4(lo.x, lo.y, hi.x, hi.y);
    }
}

// ---------------- attention finalize: sum NP partials, normalize, +bias, relu ----------------
template <int D, int NP>
__global__ __launch_bounds__(256) void attn_final(
    const float* __restrict__ bias, float* __restrict__ out)
{
    int idx = blockIdx.x * 256 + threadIdx.x;   // float4 index, total 1024*D/4
    int e0 = idx * 4;
    int j = e0 / D, f = e0 % D;
    float4 p0 = *(const float4*)&g_psum[j * 8];
    float4 p1 = *(const float4*)&g_psum[j * 8 + 4];
    float inv = 1.0f / (p0.x + p0.y + p0.z + p0.w + p1.x + p1.y + p1.z + p1.w);
    float4 a = make_float4(0.f, 0.f, 0.f, 0.f);
#pragma unroll
    for (int p = 0; p < NP; p++) {
        float4 vv = *(const float4*)&g_apart[((size_t)p * 1024 + j) * D + f];
        a.x += vv.x; a.y += vv.y; a.z += vv.z; a.w += vv.w;
    }
    float4 bv = *(const float4*)&bias[f];
    float y0 = a.x * inv + bv.x; y0 = y0 > 0.f ? y0 : 0.f;
    float y1 = a.y * inv + bv.y; y1 = y1 > 0.f ? y1 : 0.f;
    float y2 = a.z * inv + bv.z; y2 = y2 > 0.f ? y2 : 0.f;
    float y3 = a.w * inv + bv.w; y3 = y3 > 0.f ? y3 : 0.f;
    *(float4*)&out[(size_t)j * D + f] = make_float4(y0, y1, y2, y3);
}

// ---------------- fused mean pool + linear(128->10) + log_softmax, 1 block/image ----------------
__global__ __launch_bounds__(256) void pool_final_kernel(
    const float* __restrict__ W, const float* __restrict__ bo,
    float* __restrict__ out)
{
    __shared__ float red[256];
    __shared__ float meanv[128];
    __shared__ float logits[10];
    __shared__ float stats[2];
    int b = blockIdx.x;
    int t = threadIdx.x;
    int f = t & 127;                 // feature
    int half = t >> 7;               // node half
    const float* base = g_x2 + ((size_t)b * 1024 + half * 512) * 128 + f;
    float acc = 0.f;
#pragma unroll 8
    for (int n = 0; n < 512; n++) acc += base[(size_t)n * 128];
    red[t] = acc;
    __syncthreads();
    if (t < 128) meanv[t] = (red[t] + red[t + 128]) * (1.0f / 1024.0f);
    __syncthreads();
    if (t < 10) {
        float lg = bo[t];
        for (int ff = 0; ff < 128; ff++) lg += meanv[ff] * W[ff * 10 + t];
        logits[t] = lg;
    }
    __syncthreads();
    if (t == 0) {
        float mv = -1e30f;
        for (int k = 0; k < 10; k++) mv = fmaxf(mv, logits[k]);
        float se = 0.f;
        for (int k = 0; k < 10; k++) se += expf(logits[k] - mv);
        stats[0] = mv;
        stats[1] = logf(se);
    }
    __syncthreads();
    if (t < 10) out[b * 10 + t] = logits[t] - stats[0] - stats[1];
}

// ---------------- launch ----------------
extern "C" void kernel_launch(void* const* d_in, const int* in_sizes, int n_in,
                              void* d_out, int out_size)
{
    const float* images  = (const float*)d_in[0];
    const float* conv1_w = (const float*)d_in[1];
    const float* conv1_b = (const float*)d_in[2];
    const float* bn1_g   = (const float*)d_in[3];
    const float* bn1_b   = (const float*)d_in[4];
    const float* bn1_m   = (const float*)d_in[5];
    const float* bn1_v   = (const float*)d_in[6];
    const float* conv2_w = (const float*)d_in[7];
    const float* conv2_b = (const float*)d_in[8];
    const float* bn2_g   = (const float*)d_in[9];
    const float* bn2_b   = (const float*)d_in[10];
    const float* bn2_m   = (const float*)d_in[11];
    const float* bn2_v   = (const float*)d_in[12];
    const float* gat1_w    = (const float*)d_in[13];
    const float* gat1_asrc = (const float*)d_in[14];
    const float* gat1_adst = (const float*)d_in[15];
    const float* gat1_bias = (const float*)d_in[16];
    const float* gat2_w    = (const float*)d_in[17];
    const float* gat2_asrc = (const float*)d_in[18];
    const float* gat2_adst = (const float*)d_in[19];
    const float* gat2_bias = (const float*)d_in[20];
    const float* out_w = (const float*)d_in[21];
    const float* out_b = (const float*)d_in[22];
    float* out = (float*)d_out;

    float* nodes0 = nullptr; cudaGetSymbolAddress((void**)&nodes0, g_nodes0);
    float* h1 = nullptr;     cudaGetSymbolAddress((void**)&h1, g_h1);
    float* x1 = nullptr;     cudaGetSymbolAddress((void**)&x1, g_x1);
    float* h2 = nullptr;     cudaGetSymbolAddress((void**)&h2, g_h2);
    float* x2 = nullptr;     cudaGetSymbolAddress((void**)&x2, g_x2);
    float* s1p = nullptr;    cudaGetSymbolAddress((void**)&s1p, g_s1p);
    float* d1p = nullptr;    cudaGetSymbolAddress((void**)&d1p, g_d1p);
    float* s2p = nullptr;    cudaGetSymbolAddress((void**)&s2p, g_s2p);
    float* d2p = nullptr;    cudaGetSymbolAddress((void**)&d2p, g_d2p);

    stage1_kernel<<<2048 + 288, 256>>>(images, conv1_w, conv1_b, bn1_g, bn1_b,
                                       bn1_m, bn1_v, conv2_w);
    conv2_kernel<<<dim3(16, 2, 8), 256>>>(conv2_b, bn2_g, bn2_b, bn2_m, bn2_v);

    // GAT layer 1 (D=256: IGn=2 -> 16 partials)
    sgemm_fused<<<dim3(4, 64), 256>>>(nodes0, gat1_w, gat1_bias, gat1_asrc,
                                      gat1_adst, h1, x1, s1p, d1p, 256, 128);
    attn_partial<256, 4><<<dim3(64, 8), 256>>>(h1, s1p, d1p);
    attn_final<256, 16><<<256, 256>>>(gat1_bias, x1);

    // GAT layer 2 (D=128: IGn=4 -> 32 partials)
    sgemm_fused<<<dim3(2, 64), 256>>>(x1, gat2_w, gat2_bias, gat2_asrc,
                                      gat2_adst, h2, x2, s2p, d2p, 128, 256);
    attn_partial<128, 2><<<dim3(64, 8), 256>>>(h2, s2p, d2p);
    attn_final<128, 32><<<128, 256>>>(gat2_bias, x2);

    pool_final_kernel<<<8, 256>>>(out_w, out_b, out);
}

// round 16
// speedup vs baseline: 1.1060x; 1.1060x over previous
#include <cuda_runtime.h>
#include <math.h>

typedef unsigned long long ull;
#define BN_EPS 1e-5f

// ---------------- scratch ----------------
__device__ float g_pool[8 * 64 * 32 * 32];
__device__ float g_w2t[576 * 128];
__device__ float g_nodes0[8192 * 128];
__device__ float g_h1[8192 * 256];
__device__ float g_x1[8192 * 256];
__device__ float g_h2[8192 * 128];
__device__ float g_x2[8192 * 128];
__device__ float g_s1p[1024 * 4];
__device__ float g_d1p[1024 * 4];
__device__ float g_s2p[1024 * 2];
__device__ float g_d2p[1024 * 2];
__device__ float g_psum[1024 * 8];
__device__ float g_apart[8 * 1024 * 256];
__device__ float g_part[64 * 128];

// ---------------- f32x2 helpers ----------------
__device__ __forceinline__ unsigned sptr(const void* p) {
    return (unsigned)__cvta_generic_to_shared(p);
}
__device__ __forceinline__ void lds2(ull& a, ull& b, unsigned addr) {
    asm volatile("ld.shared.v2.b64 {%0,%1},[%2];" : "=l"(a), "=l"(b) : "r"(addr));
}
__device__ __forceinline__ ull dupf(float v) {
    unsigned u = __float_as_uint(v);
    ull r;
    asm("mov.b64 %0,{%1,%1};" : "=l"(r) : "r"(u));
    return r;
}
__device__ __forceinline__ void ffma2(ull& d, ull a, ull b) {
    asm("fma.rn.f32x2 %0,%1,%2,%0;" : "+l"(d) : "l"(a), "l"(b));
}
union F2U { ull u; float2 f; };
__device__ __forceinline__ float2 upk(ull u) { F2U x; x.u = u; return x.f; }

// ---------------- stage1: conv1+bn+relu+pool | w2 transpose ----------------
__global__ __launch_bounds__(256) void stage1_kernel(
    const float* __restrict__ img, const float* __restrict__ w,
    const float* __restrict__ cb, const float* __restrict__ g,
    const float* __restrict__ bb, const float* __restrict__ m,
    const float* __restrict__ v, const float* __restrict__ w2)
{
    __shared__ float ws[1728];
    __shared__ float sc_s[64], sh_s[64];
    int t = threadIdx.x;

    if (blockIdx.x >= 2048) {
        int i = (blockIdx.x - 2048) * 256 + t;      // 73728 total
        int rem = i >> 7, oc = i & 127;
        g_w2t[i] = w2[oc * 576 + rem];
        return;
    }

    for (int i = t; i < 1728; i += 256) ws[i] = w[i];
    if (t < 64) {
        float sc = g[t] * rsqrtf(v[t] + BN_EPS);
        sc_s[t] = sc;
        sh_s[t] = bb[t] - m[t] * sc + cb[t] * sc;
    }
    __syncthreads();

    int idx = blockIdx.x * 256 + t;
    int pw = idx & 31;
    int ph = (idx >> 5) & 31;
    int c  = (idx >> 10) & 63;
    int b  = idx >> 16;

    float win[3][4][4];
    int h0 = 2 * ph - 1, w0 = 2 * pw - 1;
#pragma unroll
    for (int ic = 0; ic < 3; ic++) {
        const float* ip = img + (b * 3 + ic) * 4096;
#pragma unroll
        for (int r = 0; r < 4; r++) {
            int ih = h0 + r;
            bool rok = (unsigned)ih < 64u;
#pragma unroll
            for (int cc = 0; cc < 4; cc++) {
                int iw = w0 + cc;
                win[ic][r][cc] = (rok && (unsigned)iw < 64u) ? ip[ih * 64 + iw] : 0.0f;
            }
        }
    }
    const float* wc = ws + c * 27;
    float sc = sc_s[c], sh = sh_s[c];
    float mx = 0.0f;
#pragma unroll
    for (int dh = 0; dh < 2; dh++)
#pragma unroll
    for (int dw = 0; dw < 2; dw++) {
        float s = 0.f;
#pragma unroll
        for (int ic = 0; ic < 3; ic++)
#pragma unroll
        for (int kh = 0; kh < 3; kh++)
#pragma unroll
        for (int kw = 0; kw < 3; kw++)
            s += win[ic][dh + kh][dw + kw] * wc[ic * 9 + kh * 3 + kw];
        float y = s * sc + sh;
        y = y > 0.f ? y : 0.f;
        mx = fmaxf(mx, y);
    }
    g_pool[idx] = mx;
}

// ---------------- conv2: grid (16 row-pairs, 2 oc-halves, 8 imgs) ----------------
__global__ __launch_bounds__(256) void conv2_kernel(
    const float* __restrict__ cb, const float* __restrict__ g,
    const float* __restrict__ bb, const float* __restrict__ m,
    const float* __restrict__ v)
{
    __shared__ float in_s[1088];   // 8ic x 4rows x 34cols
    __shared__ float w_s[4608];    // 72 x 64
    int t  = threadIdx.x;
    int h0 = blockIdx.x * 2;
    int oh = blockIdx.y;
    int b  = blockIdx.z;
    int px = t & 31;
    int cq = t >> 5;
    unsigned wsa = sptr(w_s);

    ull acc[2][4];
#pragma unroll
    for (int r = 0; r < 2; r++)
#pragma unroll
    for (int j = 0; j < 4; j++) acc[r][j] = 0ull;

    const float4* w2t4 = (const float4*)g_w2t;
    for (int ic0 = 0; ic0 < 64; ic0 += 8) {
        __syncthreads();
        for (int i = t; i < 1152; i += 256) {
            int rem = i >> 4, q = i & 15;
            ((float4*)w_s)[i] = w2t4[(ic0 * 9 + rem) * 32 + oh * 16 + q];
        }
        for (int i = t; i < 1088; i += 256) {
            int ic  = i / 136;
            int rem = i - ic * 136;
            int r   = rem / 34;
            int col = rem - r * 34;
            int ri = h0 - 1 + r;
            int ci = col - 1;
            float val = 0.f;
            if ((unsigned)ri < 32u && (unsigned)ci < 32u)
                val = g_pool[((b * 64 + ic0 + ic) * 32 + ri) * 32 + ci];
            in_s[i] = val;
        }
        __syncthreads();
#pragma unroll 2
        for (int ic8 = 0; ic8 < 8; ic8++) {
#pragma unroll
            for (int kr = 0; kr < 3; kr++) {
                const float* prow = in_s + (ic8 * 4 + kr) * 34 + px;
#pragma unroll
                for (int kc = 0; kc < 3; kc++) {
                    unsigned wa = wsa + (((ic8 * 9 + kr * 3 + kc) << 6) + (cq << 3)) * 4u;
                    ull w0, w1, w2x, w3;
                    lds2(w0, w1, wa);
                    lds2(w2x, w3, wa + 16);
                    ull v0 = dupf(prow[kc]);
                    ull v1 = dupf(prow[kc + 34]);
                    ffma2(acc[0][0], v0, w0);  ffma2(acc[0][1], v0, w1);
                    ffma2(acc[0][2], v0, w2x); ffma2(acc[0][3], v0, w3);
                    ffma2(acc[1][0], v1, w0);  ffma2(acc[1][1], v1, w1);
                    ffma2(acc[1][2], v1, w2x); ffma2(acc[1][3], v1, w3);
                }
            }
        }
    }

    int cbase = oh * 64 + cq * 8;
    float scs[8], shs[8];
#pragma unroll
    for (int j = 0; j < 8; j++) {
        int c = cbase + j;
        float sc = g[c] * rsqrtf(v[c] + BN_EPS);
        scs[j] = sc;
        shs[j] = bb[c] - m[c] * sc + cb[c] * sc;
    }
#pragma unroll
    for (int r = 0; r < 2; r++) {
        int node = b * 1024 + (h0 + r) * 32 + px;
        float* op = g_nodes0 + node * 128 + cbase;
        float outv[8];
#pragma unroll
        for (int jp = 0; jp < 4; jp++) {
            float2 p = upk(acc[r][jp]);
            outv[2 * jp]     = p.x;
            outv[2 * jp + 1] = p.y;
        }
#pragma unroll
        for (int j = 0; j < 8; j++) {
            float y = outv[j] * scs[j] + shs[j];
            outv[j] = y > 0.f ? y : 0.f;
        }
        *(float4*)op       = *(float4*)&outv[0];
        *(float4*)(op + 4) = *(float4*)&outv[4];
    }
}

// ---------------- SGEMM: 128x64 tile, 8x4/thread, double-buffered, fused epilogue ----------------
__global__ __launch_bounds__(256) void sgemm_fused(
    const float* __restrict__ A, const float* __restrict__ B,
    const float* __restrict__ bias, const float* __restrict__ asrc,
    const float* __restrict__ adst, float* __restrict__ H,
    float* __restrict__ X, float* __restrict__ s_part,
    float* __restrict__ d_part, int N, int K)
{
    __shared__ float As[2][16][128];
    __shared__ float Bs[2][16][64];
    int t = threadIdx.x;
    int bm = blockIdx.y * 128, bn = blockIdx.x * 64;
    int tx = t & 15, ty = t >> 4;
    int ar = t >> 1, a8 = (t & 1) * 8;
    int bk = t >> 4, bc = (t & 15) * 4;
    const float* Aload = A + (size_t)(bm + ar) * K + a8;
    const float* Bload = B + (size_t)bk * N + bn + bc;
    unsigned bsB = sptr(Bs);

    float4 pa0 = *(const float4*)(Aload);
    float4 pa1 = *(const float4*)(Aload + 4);
    float4 pb  = *(const float4*)(Bload);

    ull acc[8][2];
#pragma unroll
    for (int i = 0; i < 8; i++) { acc[i][0] = 0ull; acc[i][1] = 0ull; }

    int NC = K >> 4;
    for (int ch = 0; ch < NC; ch++) {
        int p = ch & 1;
        As[p][a8 + 0][ar] = pa0.x; As[p][a8 + 1][ar] = pa0.y;
        As[p][a8 + 2][ar] = pa0.z; As[p][a8 + 3][ar] = pa0.w;
        As[p][a8 + 4][ar] = pa1.x; As[p][a8 + 5][ar] = pa1.y;
        As[p][a8 + 6][ar] = pa1.z; As[p][a8 + 7][ar] = pa1.w;
        *(float4*)&Bs[p][bk][bc] = pb;
        __syncthreads();
        if (ch + 1 < NC) {
            pa0 = *(const float4*)(Aload + (ch + 1) * 16);
            pa1 = *(const float4*)(Aload + (ch + 1) * 16 + 4);
            pb  = *(const float4*)(Bload + (size_t)(ch + 1) * 16 * N);
        }
        unsigned bbase = bsB + (unsigned)p * 4096u + (unsigned)tx * 16u;
#pragma unroll
        for (int k = 0; k < 16; k++) {
            float4 a0 = *(const float4*)&As[p][k][ty * 8];
            float4 a1 = *(const float4*)&As[p][k][ty * 8 + 4];
            ull b01, b23;
            lds2(b01, b23, bbase + (unsigned)k * 256u);
            ull d;
            d = dupf(a0.x); ffma2(acc[0][0], d, b01); ffma2(acc[0][1], d, b23);
            d = dupf(a0.y); ffma2(acc[1][0], d, b01); ffma2(acc[1][1], d, b23);
            d = dupf(a0.z); ffma2(acc[2][0], d, b01); ffma2(acc[2][1], d, b23);
            d = dupf(a0.w); ffma2(acc[3][0], d, b01); ffma2(acc[3][1], d, b23);
            d = dupf(a1.x); ffma2(acc[4][0], d, b01); ffma2(acc[4][1], d, b23);
            d = dupf(a1.y); ffma2(acc[5][0], d, b01); ffma2(acc[5][1], d, b23);
            d = dupf(a1.z); ffma2(acc[6][0], d, b01); ffma2(acc[6][1], d, b23);
            d = dupf(a1.w); ffma2(acc[7][0], d, b01); ffma2(acc[7][1], d, b23);
        }
    }

    float c[8][4];
#pragma unroll
    for (int rr = 0; rr < 8; rr++) {
        float2 lo = upk(acc[rr][0]);
        float2 hi = upk(acc[rr][1]);
        c[rr][0] = lo.x; c[rr][1] = lo.y; c[rr][2] = hi.x; c[rr][3] = hi.y;
    }
    int col = bn + tx * 4;

    if (bm >= 1024) {
        float4 bv = *(const float4*)&bias[col];
#pragma unroll
        for (int rr = 0; rr < 8; rr++) {
            float y0 = c[rr][0] + bv.x; y0 = y0 > 0.f ? y0 : 0.f;
            float y1 = c[rr][1] + bv.y; y1 = y1 > 0.f ? y1 : 0.f;
            float y2 = c[rr][2] + bv.z; y2 = y2 > 0.f ? y2 : 0.f;
            float y3 = c[rr][3] + bv.w; y3 = y3 > 0.f ? y3 : 0.f;
            *(float4*)&X[(size_t)(bm + ty * 8 + rr) * N + col] =
                make_float4(y0, y1, y2, y3);
        }
    } else {
        float4 av = *(const float4*)&asrc[col];
        float4 dv = *(const float4*)&adst[col];
        int NB = gridDim.x;
#pragma unroll
        for (int rr = 0; rr < 8; rr++) {
            *(float4*)&H[(size_t)(bm + ty * 8 + rr) * N + col] =
                make_float4(c[rr][0], c[rr][1], c[rr][2], c[rr][3]);
            float sp = c[rr][0] * av.x + c[rr][1] * av.y + c[rr][2] * av.z + c[rr][3] * av.w;
            float dp = c[rr][0] * dv.x + c[rr][1] * dv.y + c[rr][2] * dv.z + c[rr][3] * dv.w;
#pragma unroll
            for (int off = 8; off > 0; off >>= 1) {
                sp += __shfl_xor_sync(0xffffffffu, sp, off);
                dp += __shfl_xor_sync(0xffffffffu, dp, off);
            }
            if ((t & 15) == 0) {
                int row = bm + ty * 8 + rr;
                s_part[row * NB + blockIdx.x] = sp;
                d_part[row * NB + blockIdx.x] = dp;
            }
        }
    }
}

// ---------------- attention partial v3 (measured-best, round 7) ----------------
// grid (64 j-blocks of NJ=16, 8 i-splits of 128 rows) = 512 blocks.
// sd_combine fused (redundant per block). Exact softmax max via monotonicity.
template <int D, int NB>
__global__ __launch_bounds__(256) void attn_partial(
    const float* __restrict__ h, const float* __restrict__ s_part,
    const float* __restrict__ d_part)
{
    const int NJ = 16, IROWS = 128, PAD = 20;
    const int FG  = D / 4;             // 64 (D=256) / 32 (D=128)
    const int IGn = 256 / (FG * 2);    // 2 / 4
    const int RPI = IROWS / IGn;       // 64 / 32
    __shared__ float s_loc[IROWS];
    __shared__ float w_s[IROWS * PAD];     // 10 KB
    __shared__ float buf[8192];            // 32 KB (NJ*IGn*D)
    __shared__ float dv_s[NJ], mx_s[NJ];
    __shared__ float wred[8];
    __shared__ float smax_sh;
    int t = threadIdx.x;
    int j0 = blockIdx.x * NJ;
    int by = blockIdx.y;
    int i0 = by * IROWS;

    // fused sd_combine: all 1024 s sums (keep our 128), global max, our 16 d's
    float lmax = -1e30f;
#pragma unroll
    for (int k = 0; k < 4; k++) {
        int i = t + k * 256;
        float s = 0.f;
#pragma unroll
        for (int nb = 0; nb < NB; nb++) s += s_part[i * NB + nb];
        if ((unsigned)(i - i0) < (unsigned)IROWS) s_loc[i - i0] = s;
        lmax = fmaxf(lmax, s);
    }
    if (t < NJ) {
        float dd = 0.f;
#pragma unroll
        for (int nb = 0; nb < NB; nb++) dd += d_part[(j0 + t) * NB + nb];
        dv_s[t] = dd;
    }
#pragma unroll
    for (int o = 16; o > 0; o >>= 1)
        lmax = fmaxf(lmax, __shfl_xor_sync(0xffffffffu, lmax, o));
    if ((t & 31) == 0) wred[t >> 5] = lmax;
    __syncthreads();
    if (t == 0) {
        float mv = wred[0];
#pragma unroll
        for (int k = 1; k < 8; k++) mv = fmaxf(mv, wred[k]);
        smax_sh = mv;
    }
    __syncthreads();
    if (t < NJ) {
        float e = smax_sh + dv_s[t];
        mx_s[t] = e > 0.f ? e : 0.2f * e;
    }
    __syncthreads();

    // phase 1: w for this block's 128 rows x 16 j (t -> row t&127, j-half t>>7)
    {
        int il = t & 127, jh = t >> 7;
        float si = s_loc[il];
#pragma unroll
        for (int jj = 0; jj < 8; jj++) {
            int j = jh * 8 + jj;
            float e = si + dv_s[j];
            e = e > 0.f ? e : 0.2f * e;
            w_s[il * PAD + j] = __expf(e - mx_s[j]);
        }
    }
    __syncthreads();

    // partial denominators
    {
        int lane = t & 31, wj = t >> 5;
#pragma unroll
        for (int c = wj; c < NJ; c += 8) {
            float sval = 0.f;
            for (int r = lane; r < IROWS; r += 32) sval += w_s[r * PAD + c];
#pragma unroll
            for (int o = 16; o > 0; o >>= 1)
                sval += __shfl_xor_sync(0xffffffffu, sval, o);
            if (lane == 0) g_psum[(j0 + c) * 8 + by] = sval;
        }
    }

    // phase 2: thread = (4 features fg, 8 dests jq-half, i-subrange ig)
    int fg = t & (FG - 1);
    int jq = (t / FG) & 1;
    int ig = t / (FG * 2);
    ull acc2[8][2];
#pragma unroll
    for (int j = 0; j < 8; j++) { acc2[j][0] = 0ull; acc2[j][1] = 0ull; }
    const float* hp = h + (size_t)(i0 + ig * RPI) * D + fg * 4;
    const float* wp = w_s + (ig * RPI) * PAD + jq * 8;
#pragma unroll 4
    for (int ii = 0; ii < RPI; ii++) {
        ulonglong2 hv = *(const ulonglong2*)(hp + (size_t)ii * D);
        float4 w0 = *(const float4*)(wp + ii * PAD);
        float4 w1 = *(const float4*)(wp + ii * PAD + 4);
        ull d;
        d = dupf(w0.x); ffma2(acc2[0][0], d, hv.x); ffma2(acc2[0][1], d, hv.y);
        d = dupf(w0.y); ffma2(acc2[1][0], d, hv.x); ffma2(acc2[1][1], d, hv.y);
        d = dupf(w0.z); ffma2(acc2[2][0], d, hv.x); ffma2(acc2[2][1], d, hv.y);
        d = dupf(w0.w); ffma2(acc2[3][0], d, hv.x); ffma2(acc2[3][1], d, hv.y);
        d = dupf(w1.x); ffma2(acc2[4][0], d, hv.x); ffma2(acc2[4][1], d, hv.y);
        d = dupf(w1.y); ffma2(acc2[5][0], d, hv.x); ffma2(acc2[5][1], d, hv.y);
        d = dupf(w1.z); ffma2(acc2[6][0], d, hv.x); ffma2(acc2[6][1], d, hv.y);
        d = dupf(w1.w); ffma2(acc2[7][0], d, hv.x); ffma2(acc2[7][1], d, hv.y);
    }
    // stash per-(j, ig) partials: buf[j][ig][D]
#pragma unroll
    for (int jj = 0; jj < 8; jj++) {
        int j = jq * 8 + jj;
        float2 lo = upk(acc2[jj][0]);
        float2 hi = upk(acc2[jj][1]);
        *(float4*)&buf[(j * IGn + ig) * D + fg * 4] =
            make_float4(lo.x, lo.y, hi.x, hi.y);
    }
    __syncthreads();

    // combine ig groups, write unnormalized partial output
    const int K4 = (NJ * D) / (4 * 256);   // 4 (D=256) / 2 (D=128)
#pragma unroll
    for (int k = 0; k < K4; k++) {
        int o4 = t + k * 256;
        int j = o4 / FG, f4 = o4 % FG;
        float4 sum = make_float4(0.f, 0.f, 0.f, 0.f);
#pragma unroll
        for (int g2 = 0; g2 < IGn; g2++) {
            float4 vv = *(const float4*)&buf[(j * IGn + g2) * D + f4 * 4];
            sum.x += vv.x; sum.y += vv.y; sum.z += vv.z; sum.w += vv.w;
        }
        *(float4*)&g_apart[((size_t)by * 1024 + j0 + j) * D + f4 * 4] = sum;
    }
}

// ---------------- attention finalize: sum 8 partials, normalize, +bias, relu ----------------
template <int D>
__global__ __launch_bounds__(256) void attn_final(
    const float* __restrict__ bias, float* __restrict__ out)
{
    int idx = blockIdx.x * 256 + threadIdx.x;   // float4 index, total 1024*D/4
    int e0 = idx * 4;
    int j = e0 / D, f = e0 % D;
    float4 p0 = *(const float4*)&g_psum[j * 8];
    float4 p1 = *(const float4*)&g_psum[j * 8 + 4];
    float inv = 1.0f / (p0.x + p0.y + p0.z + p0.w + p1.x + p1.y + p1.z + p1.w);
    float4 a = make_float4(0.f, 0.f, 0.f, 0.f);
#pragma unroll
    for (int p = 0; p < 8; p++) {
        float4 vv = *(const float4*)&g_apart[((size_t)p * 1024 + j) * D + f];
        a.x += vv.x; a.y += vv.y; a.z += vv.z; a.w += vv.w;
    }
    float4 bv = *(const float4*)&bias[f];
    float y0 = a.x * inv + bv.x; y0 = y0 > 0.f ? y0 : 0.f;
    float y1 = a.y * inv + bv.y; y1 = y1 > 0.f ? y1 : 0.f;
    float y2 = a.z * inv + bv.z; y2 = y2 > 0.f ? y2 : 0.f;
    float y3 = a.w * inv + bv.w; y3 = y3 > 0.f ? y3 : 0.f;
    *(float4*)&out[(size_t)j * D + f] = make_float4(y0, y1, y2, y3);
}

// ---------------- mean pool stage 1 ----------------
__global__ __launch_bounds__(128) void pool_partial_kernel()
{
    int b = blockIdx.x >> 3, ch = blockIdx.x & 7, t = threadIdx.x;
    const float* base = g_x2 + (b * 1024 + ch * 128) * 128;
    float acc = 0.f;
    for (int n = 0; n < 128; n++) acc += base[n * 128 + t];
    g_part[blockIdx.x * 128 + t] = acc;
}

// ---------------- stage 2: combine + linear + log_softmax ----------------
__global__ __launch_bounds__(128) void final_kernel(
    const float* __restrict__ W, const float* __restrict__ bo,
    float* __restrict__ out)
{
    __shared__ float meanv[128];
    __shared__ float logits[10];
    __shared__ float stats[2];
    int b = blockIdx.x;
    int t = threadIdx.x;
    float acc = 0.f;
#pragma unroll
    for (int k = 0; k < 8; k++) acc += g_part[(b * 8 + k) * 128 + t];
    meanv[t] = acc * (1.0f / 1024.0f);
    __syncthreads();
    if (t < 10) {
        float lg = bo[t];
        for (int f = 0; f < 128; f++) lg += meanv[f] * W[f * 10 + t];
        logits[t] = lg;
    }
    __syncthreads();
    if (t == 0) {
        float mv = -1e30f;
        for (int k = 0; k < 10; k++) mv = fmaxf(mv, logits[k]);
        float se = 0.f;
        for (int k = 0; k < 10; k++) se += expf(logits[k] - mv);
        stats[0] = mv;
        stats[1] = logf(se);
    }
    __syncthreads();
    if (t < 10) out[b * 10 + t] = logits[t] - stats[0] - stats[1];
}

// ---------------- launch ----------------
extern "C" void kernel_launch(void* const* d_in, const int* in_sizes, int n_in,
                              void* d_out, int out_size)
{
    const float* images  = (const float*)d_in[0];
    const float* conv1_w = (const float*)d_in[1];
    const float* conv1_b = (const float*)d_in[2];
    const float* bn1_g   = (const float*)d_in[3];
    const float* bn1_b   = (const float*)d_in[4];
    const float* bn1_m   = (const float*)d_in[5];
    const float* bn1_v   = (const float*)d_in[6];
    const float* conv2_w = (const float*)d_in[7];
    const float* conv2_b = (const float*)d_in[8];
    const float* bn2_g   = (const float*)d_in[9];
    const float* bn2_b   = (const float*)d_in[10];
    const float* bn2_m   = (const float*)d_in[11];
    const float* bn2_v   = (const float*)d_in[12];
    const float* gat1_w    = (const float*)d_in[13];
    const float* gat1_asrc = (const float*)d_in[14];
    const float* gat1_adst = (const float*)d_in[15];
    const float* gat1_bias = (const float*)d_in[16];
    const float* gat2_w    = (const float*)d_in[17];
    const float* gat2_asrc = (const float*)d_in[18];
    const float* gat2_adst = (const float*)d_in[19];
    const float* gat2_bias = (const float*)d_in[20];
    const float* out_w = (const float*)d_in[21];
    const float* out_b = (const float*)d_in[22];
    float* out = (float*)d_out;

    float* nodes0 = nullptr; cudaGetSymbolAddress((void**)&nodes0, g_nodes0);
    float* h1 = nullptr;     cudaGetSymbolAddress((void**)&h1, g_h1);
    float* x1 = nullptr;     cudaGetSymbolAddress((void**)&x1, g_x1);
    float* h2 = nullptr;     cudaGetSymbolAddress((void**)&h2, g_h2);
    float* x2 = nullptr;     cudaGetSymbolAddress((void**)&x2, g_x2);
    float* s1p = nullptr;    cudaGetSymbolAddress((void**)&s1p, g_s1p);
    float* d1p = nullptr;    cudaGetSymbolAddress((void**)&d1p, g_d1p);
    float* s2p = nullptr;    cudaGetSymbolAddress((void**)&s2p, g_s2p);
    float* d2p = nullptr;    cudaGetSymbolAddress((void**)&d2p, g_d2p);

    stage1_kernel<<<2048 + 288, 256>>>(images, conv1_w, conv1_b, bn1_g, bn1_b,
                                       bn1_m, bn1_v, conv2_w);
    conv2_kernel<<<dim3(16, 2, 8), 256>>>(conv2_b, bn2_g, bn2_b, bn2_m, bn2_v);

    // GAT layer 1
    sgemm_fused<<<dim3(4, 64), 256>>>(nodes0, gat1_w, gat1_bias, gat1_asrc,
                                      gat1_adst, h1, x1, s1p, d1p, 256, 128);
    attn_partial<256, 4><<<dim3(64, 8), 256>>>(h1, s1p, d1p);
    attn_final<256><<<256, 256>>>(gat1_bias, x1);

    // GAT layer 2
    sgemm_fused<<<dim3(2, 64), 256>>>(x1, gat2_w, gat2_bias, gat2_asrc,
                                      gat2_adst, h2, x2, s2p, d2p, 128, 256);
    attn_partial<128, 2><<<dim3(64, 8), 256>>>(h2, s2p, d2p);
    attn_final<128><<<128, 256>>>(gat2_bias, x2);

    pool_partial_kernel<<<64, 128>>>();
    final_kernel<<<8, 128>>>(out_w, out_b, out);
}